// round 1
// baseline (speedup 1.0000x reference)
#include <cuda_runtime.h>
#include <cuda_bf16.h>
#include <math.h>
#include <stdint.h>

#define N_RULES 50000
#define N_PAD   50048   // 391 * 128
#define D_DIM   384
#define B_ROWS  8192
#define H_DIM   256
#define TOPK    8

#define BM 64
#define BN 128
#define BK 64
#define ASTRIDE 392     // 384 + 8 bf16 pad (bank-conflict break)
#define BSTRIDE 72      // 64 + 8 bf16 pad
#define KCH 6           // 384 / 64
#define NTILES (N_PAD / BN)      // 391
#define TOTCH  (NTILES * KCH)    // 2346

// ---------------- device scratch (allocation-free rule: static globals) ----
__device__ __nv_bfloat16 g_rules[(size_t)N_PAD * D_DIM];
__device__ float         g_rinv[N_PAD];
__device__ __nv_bfloat16 g_q[(size_t)B_ROWS * D_DIM];
__device__ float         g_topv[(size_t)B_ROWS * TOPK];
__device__ int           g_topi[(size_t)B_ROWS * TOPK];

// ---------------- prep kernels: L2-normalize rows, cast to bf16 ------------
__global__ void prep_rules_kernel(const float* __restrict__ src) {
    int row = blockIdx.x;
    int tid = threadIdx.x;  // 128 threads
    if (row >= N_RULES) {   // pad rows -> zeros (sims = 0, filtered by j<N check)
        for (int d = tid; d < D_DIM; d += 128)
            g_rules[(size_t)row * D_DIM + d] = __float2bfloat16(0.0f);
        if (tid == 0) g_rinv[row] = 0.0f;
        return;
    }
    const float* x = src + (size_t)row * D_DIM;
    float s = 0.0f;
    for (int d = tid; d < D_DIM; d += 128) { float v = x[d]; s += v * v; }
    __shared__ float red[4];
    for (int o = 16; o; o >>= 1) s += __shfl_xor_sync(0xffffffffu, s, o);
    if ((tid & 31) == 0) red[tid >> 5] = s;
    __syncthreads();
    if (tid == 0) {
        float t = red[0] + red[1] + red[2] + red[3];
        red[0] = 1.0f / fmaxf(sqrtf(t), 1e-12f);
    }
    __syncthreads();
    float inv = red[0];
    for (int d = tid; d < D_DIM; d += 128)
        g_rules[(size_t)row * D_DIM + d] = __float2bfloat16(x[d] * inv);
    if (tid == 0) g_rinv[row] = inv;
}

__global__ void prep_q_kernel(const float* __restrict__ src) {
    int row = blockIdx.x;
    int tid = threadIdx.x;  // 128 threads
    const float* x = src + (size_t)row * D_DIM;
    float s = 0.0f;
    for (int d = tid; d < D_DIM; d += 128) { float v = x[d]; s += v * v; }
    __shared__ float red[4];
    for (int o = 16; o; o >>= 1) s += __shfl_xor_sync(0xffffffffu, s, o);
    if ((tid & 31) == 0) red[tid >> 5] = s;
    __syncthreads();
    if (tid == 0) {
        float t = red[0] + red[1] + red[2] + red[3];
        red[0] = 1.0f / fmaxf(sqrtf(t), 1e-12f);
    }
    __syncthreads();
    float inv = red[0];
    for (int d = tid; d < D_DIM; d += 128)
        g_q[(size_t)row * D_DIM + d] = __float2bfloat16(x[d] * inv);
}

// ---------------- fused sims GEMM + streaming top-k ------------------------
struct __align__(16) SimsSmem {
    __nv_bfloat16 As[BM * ASTRIDE];        // resident q tile, full K
    __nv_bfloat16 Bs[2][BN * BSTRIDE];     // double-buffered rules chunk
    float topv[BM * TOPK];
    int   topi[BM * TOPK];
    float thr[BM];
    int   lck[BM];
};

__device__ __forceinline__ void cp_async16(void* smem, const void* gmem) {
    uint32_t s = (uint32_t)__cvta_generic_to_shared(smem);
    asm volatile("cp.async.cg.shared.global [%0], [%1], 16;\n" :: "r"(s), "l"(gmem));
}

__device__ __forceinline__ void issue_b_chunk(SimsSmem* sm, int tid, int ch) {
    int t  = ch / KCH;
    int kc = ch - t * KCH;
    const __nv_bfloat16* src = g_rules + (size_t)t * (BN * D_DIM) + kc * BK;
    __nv_bfloat16* bs = sm->Bs[ch & 1];
    #pragma unroll
    for (int i = 0; i < 4; ++i) {            // 128 rows * 8 uint4 = 1024 / 256 threads
        int e  = tid + i * 256;
        int r  = e >> 3;
        int c8 = e & 7;
        cp_async16(bs + r * BSTRIDE + c8 * 8, src + (size_t)r * D_DIM + c8 * 8);
    }
    asm volatile("cp.async.commit_group;\n" ::: "memory");
}

__device__ __forceinline__ void mma16816(float* c, const uint32_t* a,
                                         uint32_t b0, uint32_t b1) {
    asm volatile(
        "mma.sync.aligned.m16n8k16.row.col.f32.bf16.bf16.f32 "
        "{%0,%1,%2,%3}, {%4,%5,%6,%7}, {%8,%9}, {%0,%1,%2,%3};\n"
        : "+f"(c[0]), "+f"(c[1]), "+f"(c[2]), "+f"(c[3])
        : "r"(a[0]), "r"(a[1]), "r"(a[2]), "r"(a[3]), "r"(b0), "r"(b1));
}

__device__ void topk_insert(SimsSmem* sm, int r, float v, int j) {
    bool done = false;
    while (!done) {
        if (atomicCAS(&sm->lck[r], 0, 1) == 0) {
            volatile float* tv = sm->topv + r * TOPK;
            volatile int*   ti = sm->topi + r * TOPK;
            float mn = tv[0]; int mp = 0;
            #pragma unroll
            for (int p = 1; p < TOPK; ++p) { float x = tv[p]; if (x < mn) { mn = x; mp = p; } }
            if (v > mn) {
                tv[mp] = v;
                ti[mp] = j;
                float nm = v;
                #pragma unroll
                for (int p = 0; p < TOPK; ++p) { float x = tv[p]; if (x < nm) nm = x; }
                sm->thr[r] = nm;
            }
            __threadfence_block();
            atomicExch(&sm->lck[r], 0);
            done = true;
        }
    }
}

__global__ __launch_bounds__(256, 1)
void sims_topk_kernel() {
    extern __shared__ char smraw[];
    SimsSmem* sm = reinterpret_cast<SimsSmem*>(smraw);
    const int tid    = threadIdx.x;
    const int lane   = tid & 31;
    const int wid    = tid >> 5;
    const int warp_m = wid & 1;   // 0..1  (32-row slab)
    const int warp_n = wid >> 1;  // 0..3  (32-col slab)
    const int row0   = blockIdx.x * BM;

    // init top-k state
    for (int i = tid; i < BM * TOPK; i += 256) { sm->topv[i] = -3.0e38f; sm->topi[i] = 0; }
    for (int i = tid; i < BM; i += 256)        { sm->thr[i]  = -3.0e38f; sm->lck[i]  = 0; }

    // resident A load: 64 rows x 384 bf16 (48 uint4 per row)
    {
        const uint4* gq = reinterpret_cast<const uint4*>(g_q + (size_t)row0 * D_DIM);
        for (int i = tid; i < BM * 48; i += 256) {
            int r = i / 48, c8 = i % 48;
            uint4 v = gq[(size_t)r * 48 + c8];
            *reinterpret_cast<uint4*>(reinterpret_cast<char*>(sm->As) + r * (ASTRIDE * 2) + c8 * 16) = v;
        }
    }
    __syncthreads();

    volatile float* vthr = sm->thr;
    float creg[2][4][4];

    issue_b_chunk(sm, tid, 0);

    int t = 0, kc = 0;
    for (int ch = 0; ch < TOTCH; ++ch) {
        if (kc == 0) {
            #pragma unroll
            for (int mi = 0; mi < 2; ++mi)
                #pragma unroll
                for (int ni = 0; ni < 4; ++ni)
                    #pragma unroll
                    for (int e = 0; e < 4; ++e) creg[mi][ni][e] = 0.0f;
        }

        asm volatile("cp.async.wait_group 0;\n" ::: "memory");
        __syncthreads();
        if (ch + 1 < TOTCH) issue_b_chunk(sm, tid, ch + 1);

        const __nv_bfloat16* bs = sm->Bs[ch & 1];

        #pragma unroll
        for (int ks = 0; ks < 4; ++ks) {
            uint32_t a[2][4];
            #pragma unroll
            for (int mi = 0; mi < 2; ++mi) {
                int r = warp_m * 32 + mi * 16 + (lane >> 2);
                int c = kc * 64 + ks * 16 + (lane & 3) * 2;
                const __nv_bfloat16* ab = sm->As + r * ASTRIDE + c;
                a[mi][0] = *reinterpret_cast<const uint32_t*>(ab);
                a[mi][1] = *reinterpret_cast<const uint32_t*>(ab + 8 * ASTRIDE);
                a[mi][2] = *reinterpret_cast<const uint32_t*>(ab + 8);
                a[mi][3] = *reinterpret_cast<const uint32_t*>(ab + 8 * ASTRIDE + 8);
            }
            #pragma unroll
            for (int ni = 0; ni < 4; ++ni) {
                int n = warp_n * 32 + ni * 8 + (lane >> 2);
                int k = ks * 16 + (lane & 3) * 2;
                const __nv_bfloat16* bb = bs + n * BSTRIDE + k;
                uint32_t b0 = *reinterpret_cast<const uint32_t*>(bb);
                uint32_t b1 = *reinterpret_cast<const uint32_t*>(bb + 8);
                mma16816(creg[0][ni], a[0], b0, b1);
                mma16816(creg[1][ni], a[1], b0, b1);
            }
        }

        if (kc == KCH - 1) {
            int j0 = t * BN;
            #pragma unroll
            for (int mi = 0; mi < 2; ++mi) {
                #pragma unroll
                for (int ni = 0; ni < 4; ++ni) {
                    int rbase = warp_m * 32 + mi * 16 + (lane >> 2);
                    int cbase = warp_n * 32 + ni * 8 + (lane & 3) * 2;
                    #pragma unroll
                    for (int e = 0; e < 4; ++e) {
                        int r = rbase + ((e >= 2) ? 8 : 0);
                        int j = j0 + cbase + (e & 1);
                        float v = creg[mi][ni][e];
                        if (j < N_RULES && v > vthr[r]) topk_insert(sm, r, v, j);
                    }
                }
            }
        }
        __syncthreads();

        if (++kc == KCH) { kc = 0; ++t; }
    }

    // write per-row top-k
    for (int i = tid; i < BM * TOPK; i += 256) {
        g_topv[(size_t)row0 * TOPK + i] = sm->topv[i];
        g_topi[(size_t)row0 * TOPK + i] = sm->topi[i];
    }
}

// ---------------- epilogue: softmax -> gather -> gelu(Wx+b) -> LN ----------
#define ER 16
__global__ __launch_bounds__(256)
void epilogue_kernel(const float* __restrict__ s0,
                     const float* __restrict__ rules_raw,
                     const float* __restrict__ W,
                     const float* __restrict__ bvec,
                     const float* __restrict__ alpha_p,
                     const float* __restrict__ gamma,
                     const float* __restrict__ beta,
                     float* __restrict__ out) {
    __shared__ float ctx[ER][D_DIM];
    __shared__ float xs[ER][H_DIM];
    __shared__ float w8[ER][TOPK];
    __shared__ int   i8[ER][TOPK];
    __shared__ float mu_s[ER], rs_s[ER];

    const int tid = threadIdx.x;  // 256
    const int r0  = blockIdx.x * ER;

    if (tid < ER) {
        int r = r0 + tid;
        float v[TOPK];
        float m = -3.0e38f;
        #pragma unroll
        for (int k = 0; k < TOPK; ++k) {
            v[k] = g_topv[(size_t)r * TOPK + k];
            i8[tid][k] = g_topi[(size_t)r * TOPK + k];
            m = fmaxf(m, v[k]);
        }
        float s = 0.0f;
        #pragma unroll
        for (int k = 0; k < TOPK; ++k) { v[k] = expf(v[k] - m); s += v[k]; }
        float inv = 1.0f / s;
        #pragma unroll
        for (int k = 0; k < TOPK; ++k) w8[tid][k] = v[k] * inv;
    }
    __syncthreads();

    // gather rule context: ctx[r][d] = sum_k w[k] * rules_raw[idx_k][d] * rinv[idx_k]
    for (int e = tid; e < ER * D_DIM; e += 256) {
        int r = e / D_DIM, d = e - r * D_DIM;
        float acc = 0.0f;
        #pragma unroll
        for (int k = 0; k < TOPK; ++k) {
            int idx = i8[r][k];
            acc += w8[r][k] * rules_raw[(size_t)idx * D_DIM + d] * g_rinv[idx];
        }
        ctx[r][d] = acc;
    }
    __syncthreads();

    const float alpha = *alpha_p;
    const int h = tid;  // H_DIM == blockDim == 256
    float acc[ER];
    #pragma unroll
    for (int r = 0; r < ER; ++r) acc[r] = 0.0f;

    const float4* wr = reinterpret_cast<const float4*>(W + (size_t)h * D_DIM);
    #pragma unroll 4
    for (int dq = 0; dq < D_DIM / 4; ++dq) {
        float4 w4 = wr[dq];
        #pragma unroll
        for (int r = 0; r < ER; ++r) {
            float4 c4 = *reinterpret_cast<const float4*>(&ctx[r][dq * 4]);
            acc[r] += w4.x * c4.x + w4.y * c4.y + w4.z * c4.z + w4.w * c4.w;
        }
    }
    const float bb = bvec[h];
    #pragma unroll
    for (int r = 0; r < ER; ++r) {
        float z = acc[r] + bb;
        float g = 0.5f * z * (1.0f + erff(z * 0.70710678118654752f));  // exact gelu
        xs[r][h] = s0[(size_t)(r0 + r) * H_DIM + h] + alpha * g;
    }
    __syncthreads();

    // per-row mean / variance (ddof=0), warp w handles rows w, w+8
    const int w = tid >> 5, lane = tid & 31;
    for (int rr = w; rr < ER; rr += 8) {
        float s = 0.0f, s2 = 0.0f;
        #pragma unroll
        for (int q = 0; q < 8; ++q) {
            float x = xs[rr][lane + 32 * q];
            s += x; s2 += x * x;
        }
        for (int o = 16; o; o >>= 1) {
            s  += __shfl_xor_sync(0xffffffffu, s, o);
            s2 += __shfl_xor_sync(0xffffffffu, s2, o);
        }
        if (lane == 0) {
            float mu  = s * (1.0f / 256.0f);
            float var = s2 * (1.0f / 256.0f) - mu * mu;
            mu_s[rr] = mu;
            rs_s[rr] = rsqrtf(var + 1e-5f);
        }
    }
    __syncthreads();

    const float gm = gamma[h], bt = beta[h];
    #pragma unroll
    for (int r = 0; r < ER; ++r)
        out[(size_t)(r0 + r) * H_DIM + h] = (xs[r][h] - mu_s[r]) * rs_s[r] * gm + bt;
}

// ---------------- launch ----------------------------------------------------
extern "C" void kernel_launch(void* const* d_in, const int* in_sizes, int n_in,
                              void* d_out, int out_size) {
    const float* embeddings = (const float*)d_in[0];
    const float* s0         = (const float*)d_in[1];
    const float* rules      = (const float*)d_in[2];
    const float* W          = (const float*)d_in[3];
    const float* b          = (const float*)d_in[4];
    const float* alpha      = (const float*)d_in[5];
    const float* gamma      = (const float*)d_in[6];
    const float* beta       = (const float*)d_in[7];
    float* out = (float*)d_out;
    (void)in_sizes; (void)n_in; (void)out_size;

    cudaFuncSetAttribute(sims_topk_kernel,
                         cudaFuncAttributeMaxDynamicSharedMemorySize,
                         (int)sizeof(SimsSmem));

    prep_rules_kernel<<<N_PAD, 128>>>(rules);
    prep_q_kernel<<<B_ROWS, 128>>>(embeddings);
    sims_topk_kernel<<<B_ROWS / BM, 256, sizeof(SimsSmem)>>>();
    epilogue_kernel<<<B_ROWS / ER, 256>>>(s0, rules, W, b, alpha, gamma, beta, out);
}

// round 3
// speedup vs baseline: 1.1248x; 1.1248x over previous
#include <cuda_runtime.h>
#include <cuda_bf16.h>
#include <math.h>
#include <stdint.h>
#include <float.h>

#define N_RULES 50000
#define N_PAD   50048            // 782 * 64
#define NHALF   25024            // rules per CTA-half
#define TILES   391              // NHALF / 64
#define D_DIM   384
#define B_ROWS  8192
#define H_DIM   256
#define TOPK    8
#define NCAND   16               // 2 halves * 8

#define BM 128
#define BN 64
#define BK 64
#define KCH 6                    // 384 / 64
#define TOT (TILES * KCH)        // 2346
#define ASTRIDE 392              // 384 + 8  (784B row: +16B phase per row -> LDSM conflict-free)
#define BSTRIDE 72               // 64 + 8   (144B row)

// ---------------- device scratch ----------------
__device__ __nv_bfloat16 g_rules[(size_t)N_PAD * D_DIM];
__device__ float         g_rinv[N_PAD];
__device__ __nv_bfloat16 g_q[(size_t)B_ROWS * D_DIM];
__device__ float         g_topv[(size_t)B_ROWS * NCAND];
__device__ int           g_topi[(size_t)B_ROWS * NCAND];

// ---------------- smem struct ----------------
struct __align__(16) SimsSmem {
    __nv_bfloat16 As[BM * ASTRIDE];           // 100352 B
    __nv_bfloat16 Bs[3][BN * BSTRIDE];        // 27648 B
    float topv[BM * TOPK];
    int   topi[BM * TOPK];
    float thr[BM];
    int   lck[BM];
};

// ---------------- PTX helpers ----------------
__device__ __forceinline__ uint32_t smem_u32(const void* p) {
    uint32_t a;
    asm("{ .reg .u64 t; cvta.to.shared.u64 t, %1; cvt.u32.u64 %0, t; }" : "=r"(a) : "l"(p));
    return a;
}
__device__ __forceinline__ void cp16(uint32_t dst, const void* src) {
    asm volatile("cp.async.cg.shared.global [%0], [%1], 16;" :: "r"(dst), "l"(src));
}
__device__ __forceinline__ void ldsm_x4(uint32_t* r, uint32_t addr) {
    asm volatile("ldmatrix.sync.aligned.m8n8.x4.shared.b16 {%0,%1,%2,%3}, [%4];"
                 : "=r"(r[0]), "=r"(r[1]), "=r"(r[2]), "=r"(r[3]) : "r"(addr));
}
__device__ __forceinline__ void mma16816(float* c, const uint32_t* a,
                                         uint32_t b0, uint32_t b1) {
    asm volatile(
        "mma.sync.aligned.m16n8k16.row.col.f32.bf16.bf16.f32 "
        "{%0,%1,%2,%3}, {%4,%5,%6,%7}, {%8,%9}, {%0,%1,%2,%3};\n"
        : "+f"(c[0]), "+f"(c[1]), "+f"(c[2]), "+f"(c[3])
        : "r"(a[0]), "r"(a[1]), "r"(a[2]), "r"(a[3]), "r"(b0), "r"(b1));
}

// ---------------- prep kernels ----------------
__global__ void prep_rules_kernel(const float* __restrict__ src) {
    int row = blockIdx.x;
    int tid = threadIdx.x;  // 128
    if (row >= N_RULES) {
        for (int d = tid; d < D_DIM; d += 128)
            g_rules[(size_t)row * D_DIM + d] = __float2bfloat16(0.0f);
        if (tid == 0) g_rinv[row] = 0.0f;
        return;
    }
    const float* x = src + (size_t)row * D_DIM;
    float s = 0.0f;
    for (int d = tid; d < D_DIM; d += 128) { float v = x[d]; s += v * v; }
    __shared__ float red[4];
    for (int o = 16; o; o >>= 1) s += __shfl_xor_sync(0xffffffffu, s, o);
    if ((tid & 31) == 0) red[tid >> 5] = s;
    __syncthreads();
    if (tid == 0) {
        float t = red[0] + red[1] + red[2] + red[3];
        red[0] = 1.0f / fmaxf(sqrtf(t), 1e-12f);
    }
    __syncthreads();
    float inv = red[0];
    for (int d = tid; d < D_DIM; d += 128)
        g_rules[(size_t)row * D_DIM + d] = __float2bfloat16(x[d] * inv);
    if (tid == 0) g_rinv[row] = inv;
}

__global__ void prep_q_kernel(const float* __restrict__ src) {
    int row = blockIdx.x;
    int tid = threadIdx.x;  // 128
    const float* x = src + (size_t)row * D_DIM;
    float s = 0.0f;
    for (int d = tid; d < D_DIM; d += 128) { float v = x[d]; s += v * v; }
    __shared__ float red[4];
    for (int o = 16; o; o >>= 1) s += __shfl_xor_sync(0xffffffffu, s, o);
    if ((tid & 31) == 0) red[tid >> 5] = s;
    __syncthreads();
    if (tid == 0) {
        float t = red[0] + red[1] + red[2] + red[3];
        red[0] = 1.0f / fmaxf(sqrtf(t), 1e-12f);
    }
    __syncthreads();
    float inv = red[0];
    for (int d = tid; d < D_DIM; d += 128)
        g_q[(size_t)row * D_DIM + d] = __float2bfloat16(x[d] * inv);
}

// ---------------- fused sims GEMM + streaming top-k ------------------------
__device__ __forceinline__ void issue_b_chunk(SimsSmem* sm, uint32_t sbB,
                                              int tid, int ch, int rule0) {
    int t  = ch / KCH;
    int kc = ch - t * KCH;
    const __nv_bfloat16* src = g_rules + ((size_t)rule0 + (size_t)t * BN) * D_DIM + kc * BK;
    uint32_t bbase = sbB + (uint32_t)(ch % 3) * (BN * BSTRIDE * 2);
    #pragma unroll
    for (int i = 0; i < 2; ++i) {   // 64 rows * 8 uint4 = 512 / 256 thr
        int e = tid + i * 256;
        int r = e >> 3;
        int u = e & 7;
        cp16(bbase + (uint32_t)(r * BSTRIDE + u * 8) * 2, src + (size_t)r * D_DIM + u * 8);
    }
    asm volatile("cp.async.commit_group;" ::: "memory");
}

__device__ void topk_insert(SimsSmem* sm, int r, float v, int j) {
    bool done = false;
    while (!done) {
        if (atomicCAS(&sm->lck[r], 0, 1) == 0) {
            volatile float* tv = sm->topv + r * TOPK;
            volatile int*   ti = sm->topi + r * TOPK;
            float mn = tv[0]; int mp = 0;
            #pragma unroll
            for (int p = 1; p < TOPK; ++p) { float x = tv[p]; if (x < mn) { mn = x; mp = p; } }
            if (v > mn) {
                tv[mp] = v;
                ti[mp] = j;
                float nm = v;
                #pragma unroll
                for (int p = 0; p < TOPK; ++p) { float x = tv[p]; if (x < nm) nm = x; }
                sm->thr[r] = nm;
            }
            __threadfence_block();
            atomicExch(&sm->lck[r], 0);
            done = true;
        }
    }
}

__global__ __launch_bounds__(256, 1)
void sims_topk_kernel() {
    extern __shared__ char smraw[];
    SimsSmem* sm = reinterpret_cast<SimsSmem*>(smraw);
    const uint32_t sbA = smem_u32(sm->As);
    const uint32_t sbB = smem_u32(sm->Bs);

    const int tid    = threadIdx.x;
    const int lane   = tid & 31;
    const int wid    = tid >> 5;
    const int wm     = (wid & 3) * 32;   // 4 m-warps
    const int wn     = (wid >> 2) * 32;  // 2 n-warps
    const int grp    = blockIdx.x >> 1;
    const int half   = blockIdx.x & 1;
    const int row0   = grp * BM;
    const int rule0  = half * NHALF;

    // init top-k state
    for (int i = tid; i < BM * TOPK; i += 256) { sm->topv[i] = -FLT_MAX; sm->topi[i] = 0; }
    for (int i = tid; i < BM; i += 256)        { sm->thr[i]  = -FLT_MAX; sm->lck[i]  = 0; }

    // resident A: 128 rows x 384 bf16
    {
        const uint4* gq = reinterpret_cast<const uint4*>(g_q + (size_t)row0 * D_DIM);
        for (int i = tid; i < BM * 48; i += 256) {
            int r = i / 48, u = i - (i / 48) * 48;
            *reinterpret_cast<uint4*>(
                reinterpret_cast<char*>(sm->As) + (size_t)r * (ASTRIDE * 2) + u * 16) =
                gq[(size_t)r * 48 + u];
        }
    }

    issue_b_chunk(sm, sbB, tid, 0, rule0);
    issue_b_chunk(sm, sbB, tid, 1, rule0);

    // precomputed ldmatrix lane addressing
    const int a_row = (lane & 15);
    const int a_kof = (lane >> 4) << 3;
    const int b_row = ((lane >> 4) << 3) + (lane & 7);
    const int b_kof = ((lane >> 3) & 1) << 3;

    volatile float* vthr = sm->thr;
    float c[2][4][4];

    int t = 0, kc = 0;
    for (int ch = 0; ch < TOT; ++ch) {
        if (kc == 0) {
            #pragma unroll
            for (int mi = 0; mi < 2; ++mi)
                #pragma unroll
                for (int nq = 0; nq < 4; ++nq)
                    #pragma unroll
                    for (int e = 0; e < 4; ++e) c[mi][nq][e] = 0.0f;
        }

        if (ch == TOT - 1)
            asm volatile("cp.async.wait_group 0;" ::: "memory");
        else
            asm volatile("cp.async.wait_group 1;" ::: "memory");
        __syncthreads();

        if (ch + 2 < TOT) issue_b_chunk(sm, sbB, tid, ch + 2, rule0);

        const uint32_t bB = sbB + (uint32_t)(ch % 3) * (BN * BSTRIDE * 2);
        const int k0 = kc * BK;

        #pragma unroll
        for (int ks = 0; ks < 4; ++ks) {
            const int k = k0 + ks * 16;
            uint32_t a[2][4];
            #pragma unroll
            for (int mi = 0; mi < 2; ++mi)
                ldsm_x4(a[mi], sbA + (uint32_t)((wm + mi * 16 + a_row) * ASTRIDE + k + a_kof) * 2);
            uint32_t b[2][4];
            #pragma unroll
            for (int nt = 0; nt < 2; ++nt)
                ldsm_x4(b[nt], bB + (uint32_t)((wn + nt * 16 + b_row) * BSTRIDE + (ks * 16) + b_kof) * 2);
            #pragma unroll
            for (int mi = 0; mi < 2; ++mi)
                #pragma unroll
                for (int nq = 0; nq < 4; ++nq)
                    mma16816(c[mi][nq], a[mi], b[nq >> 1][(nq & 1) * 2], b[nq >> 1][(nq & 1) * 2 + 1]);
        }

        if (kc == KCH - 1) {
            const int jb = rule0 + t * BN;
            #pragma unroll
            for (int mi = 0; mi < 2; ++mi) {
                #pragma unroll
                for (int h = 0; h < 2; ++h) {
                    const int r = wm + mi * 16 + (lane >> 2) + h * 8;
                    float cthr = vthr[r];   // monotone: stale => only extra inserts
                    #pragma unroll
                    for (int nq = 0; nq < 4; ++nq) {
                        #pragma unroll
                        for (int e = 0; e < 2; ++e) {
                            float v = c[mi][nq][h * 2 + e];
                            int j = jb + wn + nq * 8 + (lane & 3) * 2 + e;
                            if (v > cthr && j < N_RULES) {
                                topk_insert(sm, r, v, j);
                                cthr = vthr[r];
                            }
                        }
                    }
                }
            }
        }

        if (++kc == KCH) { kc = 0; ++t; }
    }
    __syncthreads();

    // write per-row candidates (this half's top-8)
    for (int i = tid; i < BM * TOPK; i += 256) {
        int r = i >> 3, p = i & 7;
        g_topv[(size_t)(row0 + r) * NCAND + half * TOPK + p] = sm->topv[i];
        g_topi[(size_t)(row0 + r) * NCAND + half * TOPK + p] = sm->topi[i];
    }
}

// ---------------- epilogue: merge16 -> softmax -> gather -> gelu -> LN -----
#define ER 16
__global__ __launch_bounds__(256)
void epilogue_kernel(const float* __restrict__ s0,
                     const float* __restrict__ rules_raw,
                     const float* __restrict__ W,
                     const float* __restrict__ bvec,
                     const float* __restrict__ alpha_p,
                     const float* __restrict__ gamma,
                     const float* __restrict__ beta,
                     float* __restrict__ out) {
    __shared__ float ctx[ER][D_DIM];
    __shared__ float xs[ER][H_DIM];
    __shared__ float w8[ER][TOPK];
    __shared__ int   i8[ER][TOPK];
    __shared__ float mu_s[ER], rs_s[ER];

    const int tid = threadIdx.x;  // 256
    const int r0  = blockIdx.x * ER;

    if (tid < ER) {
        int r = r0 + tid;
        float cv[NCAND]; int ci[NCAND];
        #pragma unroll
        for (int q = 0; q < NCAND; ++q) {
            cv[q] = g_topv[(size_t)r * NCAND + q];
            ci[q] = g_topi[(size_t)r * NCAND + q];
        }
        float v[TOPK];
        #pragma unroll
        for (int p = 0; p < TOPK; ++p) {
            float bm = -FLT_MAX; int bq = 0;
            #pragma unroll
            for (int q = 0; q < NCAND; ++q)
                if (cv[q] > bm) { bm = cv[q]; bq = q; }
            v[p] = bm;
            #pragma unroll
            for (int q = 0; q < NCAND; ++q)
                if (q == bq) { i8[tid][p] = ci[q]; cv[q] = -FLT_MAX; }
        }
        float m = v[0];
        float s = 0.0f;
        #pragma unroll
        for (int p = 0; p < TOPK; ++p) { v[p] = expf(v[p] - m); s += v[p]; }
        float inv = 1.0f / s;
        #pragma unroll
        for (int p = 0; p < TOPK; ++p) w8[tid][p] = v[p] * inv;
    }
    __syncthreads();

    for (int e = tid; e < ER * D_DIM; e += 256) {
        int r = e / D_DIM, d = e - r * D_DIM;
        float acc = 0.0f;
        #pragma unroll
        for (int k = 0; k < TOPK; ++k) {
            int idx = i8[r][k];
            acc += w8[r][k] * rules_raw[(size_t)idx * D_DIM + d] * g_rinv[idx];
        }
        ctx[r][d] = acc;
    }
    __syncthreads();

    const float alpha = *alpha_p;
    const int h = tid;
    float acc[ER];
    #pragma unroll
    for (int r = 0; r < ER; ++r) acc[r] = 0.0f;

    const float4* wr = reinterpret_cast<const float4*>(W + (size_t)h * D_DIM);
    #pragma unroll 4
    for (int dq = 0; dq < D_DIM / 4; ++dq) {
        float4 w4 = wr[dq];
        #pragma unroll
        for (int r = 0; r < ER; ++r) {
            float4 c4 = *reinterpret_cast<const float4*>(&ctx[r][dq * 4]);
            acc[r] += w4.x * c4.x + w4.y * c4.y + w4.z * c4.z + w4.w * c4.w;
        }
    }
    const float bb = bvec[h];
    #pragma unroll
    for (int r = 0; r < ER; ++r) {
        float z = acc[r] + bb;
        float g = 0.5f * z * (1.0f + erff(z * 0.70710678118654752f));
        xs[r][h] = s0[(size_t)(r0 + r) * H_DIM + h] + alpha * g;
    }
    __syncthreads();

    const int w = tid >> 5, lane = tid & 31;
    for (int rr = w; rr < ER; rr += 8) {
        float s = 0.0f, s2 = 0.0f;
        #pragma unroll
        for (int q = 0; q < 8; ++q) {
            float x = xs[rr][lane + 32 * q];
            s += x; s2 += x * x;
        }
        for (int o = 16; o; o >>= 1) {
            s  += __shfl_xor_sync(0xffffffffu, s, o);
            s2 += __shfl_xor_sync(0xffffffffu, s2, o);
        }
        if (lane == 0) {
            float mu  = s * (1.0f / 256.0f);
            float var = s2 * (1.0f / 256.0f) - mu * mu;
            mu_s[rr] = mu;
            rs_s[rr] = rsqrtf(var + 1e-5f);
        }
    }
    __syncthreads();

    const float gm = gamma[h], bt = beta[h];
    #pragma unroll
    for (int r = 0; r < ER; ++r)
        out[(size_t)(r0 + r) * H_DIM + h] = (xs[r][h] - mu_s[r]) * rs_s[r] * gm + bt;
}

// ---------------- launch ----------------------------------------------------
extern "C" void kernel_launch(void* const* d_in, const int* in_sizes, int n_in,
                              void* d_out, int out_size) {
    const float* embeddings = (const float*)d_in[0];
    const float* s0         = (const float*)d_in[1];
    const float* rules      = (const float*)d_in[2];
    const float* W          = (const float*)d_in[3];
    const float* b          = (const float*)d_in[4];
    const float* alpha      = (const float*)d_in[5];
    const float* gamma      = (const float*)d_in[6];
    const float* beta       = (const float*)d_in[7];
    float* out = (float*)d_out;
    (void)in_sizes; (void)n_in; (void)out_size;

    cudaFuncSetAttribute(sims_topk_kernel,
                         cudaFuncAttributeMaxDynamicSharedMemorySize,
                         (int)sizeof(SimsSmem));

    prep_rules_kernel<<<N_PAD, 128>>>(rules);
    prep_q_kernel<<<B_ROWS, 128>>>(embeddings);
    sims_topk_kernel<<<128, 256, sizeof(SimsSmem)>>>();
    epilogue_kernel<<<B_ROWS / ER, 256>>>(s0, rules, W, b, alpha, gamma, beta, out);
}

// round 4
// speedup vs baseline: 1.4030x; 1.2473x over previous
#include <cuda_runtime.h>
#include <cuda_bf16.h>
#include <math.h>
#include <stdint.h>
#include <float.h>

#define N_RULES 50000
#define N_PAD   50176            // 392 * 128
#define NHALF   25088            // rules per CTA-half
#define TILES   196              // NHALF / 128
#define D_DIM   384
#define B_ROWS  8192
#define H_DIM   256
#define TOPK    8
#define NCAND   16               // 2 halves * 8

#define BM 128
#define BN 128
#define BK 64
#define KCH 6                    // 384 / 64
#define TOT (TILES * KCH)        // 1176
#define ASTRIDE 392              // 384 + 8  (conflict-free LDSM)
#define BSTRIDE 72               // 64 + 8
#define NTHREADS 512

// ---------------- device scratch ----------------
__device__ __nv_bfloat16 g_rules[(size_t)N_PAD * D_DIM];
__device__ float         g_rinv[N_PAD];
__device__ __nv_bfloat16 g_q[(size_t)B_ROWS * D_DIM];
__device__ float         g_topv[(size_t)B_ROWS * NCAND];
__device__ int           g_topi[(size_t)B_ROWS * NCAND];

// ---------------- smem struct ----------------
struct __align__(16) SimsSmem {
    __nv_bfloat16 As[BM * ASTRIDE];           // 100352 B
    __nv_bfloat16 Bs[3][BN * BSTRIDE];        // 55296 B
    float topv[BM * TOPK];
    int   topi[BM * TOPK];
    float thr[BM];
    int   lck[BM];
};

// ---------------- PTX helpers ----------------
__device__ __forceinline__ uint32_t smem_u32(const void* p) {
    uint32_t a;
    asm("{ .reg .u64 t; cvta.to.shared.u64 t, %1; cvt.u32.u64 %0, t; }" : "=r"(a) : "l"(p));
    return a;
}
__device__ __forceinline__ void cp16(uint32_t dst, const void* src) {
    asm volatile("cp.async.cg.shared.global [%0], [%1], 16;" :: "r"(dst), "l"(src));
}
__device__ __forceinline__ void ldsm_x4(uint32_t* r, uint32_t addr) {
    asm volatile("ldmatrix.sync.aligned.m8n8.x4.shared.b16 {%0,%1,%2,%3}, [%4];"
                 : "=r"(r[0]), "=r"(r[1]), "=r"(r[2]), "=r"(r[3]) : "r"(addr));
}
__device__ __forceinline__ void mma16816(float* c, const uint32_t* a,
                                         uint32_t b0, uint32_t b1) {
    asm volatile(
        "mma.sync.aligned.m16n8k16.row.col.f32.bf16.bf16.f32 "
        "{%0,%1,%2,%3}, {%4,%5,%6,%7}, {%8,%9}, {%0,%1,%2,%3};\n"
        : "+f"(c[0]), "+f"(c[1]), "+f"(c[2]), "+f"(c[3])
        : "r"(a[0]), "r"(a[1]), "r"(a[2]), "r"(a[3]), "r"(b0), "r"(b1));
}

// ---------------- prep kernels ----------------
__global__ void prep_rules_kernel(const float* __restrict__ src) {
    int row = blockIdx.x;
    int tid = threadIdx.x;  // 128
    if (row >= N_RULES) {
        for (int d = tid; d < D_DIM; d += 128)
            g_rules[(size_t)row * D_DIM + d] = __float2bfloat16(0.0f);
        if (tid == 0) g_rinv[row] = 0.0f;
        return;
    }
    const float* x = src + (size_t)row * D_DIM;
    float s = 0.0f;
    for (int d = tid; d < D_DIM; d += 128) { float v = x[d]; s += v * v; }
    __shared__ float red[4];
    for (int o = 16; o; o >>= 1) s += __shfl_xor_sync(0xffffffffu, s, o);
    if ((tid & 31) == 0) red[tid >> 5] = s;
    __syncthreads();
    if (tid == 0) {
        float t = red[0] + red[1] + red[2] + red[3];
        red[0] = 1.0f / fmaxf(sqrtf(t), 1e-12f);
    }
    __syncthreads();
    float inv = red[0];
    for (int d = tid; d < D_DIM; d += 128)
        g_rules[(size_t)row * D_DIM + d] = __float2bfloat16(x[d] * inv);
    if (tid == 0) g_rinv[row] = inv;
}

__global__ void prep_q_kernel(const float* __restrict__ src) {
    int row = blockIdx.x;
    int tid = threadIdx.x;  // 128
    const float* x = src + (size_t)row * D_DIM;
    float s = 0.0f;
    for (int d = tid; d < D_DIM; d += 128) { float v = x[d]; s += v * v; }
    __shared__ float red[4];
    for (int o = 16; o; o >>= 1) s += __shfl_xor_sync(0xffffffffu, s, o);
    if ((tid & 31) == 0) red[tid >> 5] = s;
    __syncthreads();
    if (tid == 0) {
        float t = red[0] + red[1] + red[2] + red[3];
        red[0] = 1.0f / fmaxf(sqrtf(t), 1e-12f);
    }
    __syncthreads();
    float inv = red[0];
    for (int d = tid; d < D_DIM; d += 128)
        g_q[(size_t)row * D_DIM + d] = __float2bfloat16(x[d] * inv);
}

// ---------------- fused sims GEMM + streaming top-k ------------------------
__device__ __forceinline__ void issue_b_chunk(uint32_t sbB, int tid, int ch, int rule0) {
    int t  = ch / KCH;
    int kc = ch - t * KCH;
    const __nv_bfloat16* src = g_rules + ((size_t)rule0 + (size_t)t * BN) * D_DIM + kc * BK;
    uint32_t bbase = sbB + (uint32_t)(ch % 3) * (BN * BSTRIDE * 2);
    #pragma unroll
    for (int i = 0; i < 2; ++i) {   // 128 rows * 8 uint4 = 1024 / 512 thr
        int e = tid + i * NTHREADS;
        int r = e >> 3;
        int u = e & 7;
        cp16(bbase + (uint32_t)(r * BSTRIDE + u * 8) * 2, src + (size_t)r * D_DIM + u * 8);
    }
    asm volatile("cp.async.commit_group;" ::: "memory");
}

__device__ void topk_insert(SimsSmem* sm, int r, float v, int j) {
    bool done = false;
    while (!done) {
        if (atomicCAS(&sm->lck[r], 0, 1) == 0) {
            volatile float* tv = sm->topv + r * TOPK;
            volatile int*   ti = sm->topi + r * TOPK;
            float mn = tv[0]; int mp = 0;
            #pragma unroll
            for (int p = 1; p < TOPK; ++p) { float x = tv[p]; if (x < mn) { mn = x; mp = p; } }
            if (v > mn) {
                tv[mp] = v;
                ti[mp] = j;
                float nm = v;
                #pragma unroll
                for (int p = 0; p < TOPK; ++p) { float x = tv[p]; if (x < nm) nm = x; }
                sm->thr[r] = nm;
            }
            __threadfence_block();
            atomicExch(&sm->lck[r], 0);
            done = true;
        }
    }
}

__global__ __launch_bounds__(NTHREADS, 1)
void sims_topk_kernel() {
    extern __shared__ char smraw[];
    SimsSmem* sm = reinterpret_cast<SimsSmem*>(smraw);
    const uint32_t sbA = smem_u32(sm->As);
    const uint32_t sbB = smem_u32(sm->Bs);

    const int tid    = threadIdx.x;
    const int lane   = tid & 31;
    const int wid    = tid >> 5;            // 0..15
    const int wm     = (wid & 3) * 32;      // 4 m-warps
    const int wn     = (wid >> 2) * 32;     // 4 n-warps
    const int grp    = blockIdx.x >> 1;
    const int half   = blockIdx.x & 1;
    const int row0   = grp * BM;
    const int rule0  = half * NHALF;

    // init top-k state
    for (int i = tid; i < BM * TOPK; i += NTHREADS) { sm->topv[i] = -FLT_MAX; sm->topi[i] = 0; }
    for (int i = tid; i < BM; i += NTHREADS)        { sm->thr[i]  = -FLT_MAX; sm->lck[i]  = 0; }

    // resident A: 128 rows x 384 bf16
    {
        const uint4* gq = reinterpret_cast<const uint4*>(g_q + (size_t)row0 * D_DIM);
        for (int i = tid; i < BM * 48; i += NTHREADS) {
            int r = i / 48, u = i - (i / 48) * 48;
            *reinterpret_cast<uint4*>(
                reinterpret_cast<char*>(sm->As) + (size_t)r * (ASTRIDE * 2) + u * 16) =
                gq[(size_t)r * 48 + u];
        }
    }

    issue_b_chunk(sbB, tid, 0, rule0);
    issue_b_chunk(sbB, tid, 1, rule0);

    // ldmatrix lane addressing
    const int a_row = (lane & 15);
    const int a_kof = (lane >> 4) << 3;
    const int b_row = ((lane >> 4) << 3) + (lane & 7);
    const int b_kof = ((lane >> 3) & 1) << 3;

    volatile float* vthr = sm->thr;
    float c[2][4][4];

    int t = 0, kc = 0;
    for (int ch = 0; ch < TOT; ++ch) {
        if (kc == 0) {
            #pragma unroll
            for (int mi = 0; mi < 2; ++mi)
                #pragma unroll
                for (int nq = 0; nq < 4; ++nq)
                    #pragma unroll
                    for (int e = 0; e < 4; ++e) c[mi][nq][e] = 0.0f;
        }

        if (ch == TOT - 1)
            asm volatile("cp.async.wait_group 0;" ::: "memory");
        else
            asm volatile("cp.async.wait_group 1;" ::: "memory");
        __syncthreads();

        if (ch + 2 < TOT) issue_b_chunk(sbB, tid, ch + 2, rule0);

        const uint32_t bB = sbB + (uint32_t)(ch % 3) * (BN * BSTRIDE * 2);
        const int k0 = kc * BK;

        #pragma unroll
        for (int ks = 0; ks < 4; ++ks) {
            const int k = k0 + ks * 16;
            uint32_t a[2][4];
            #pragma unroll
            for (int mi = 0; mi < 2; ++mi)
                ldsm_x4(a[mi], sbA + (uint32_t)((wm + mi * 16 + a_row) * ASTRIDE + k + a_kof) * 2);
            uint32_t b[2][4];
            #pragma unroll
            for (int nt = 0; nt < 2; ++nt)
                ldsm_x4(b[nt], bB + (uint32_t)((wn + nt * 16 + b_row) * BSTRIDE + (ks * 16) + b_kof) * 2);
            #pragma unroll
            for (int mi = 0; mi < 2; ++mi)
                #pragma unroll
                for (int nq = 0; nq < 4; ++nq)
                    mma16816(c[mi][nq], a[mi], b[nq >> 1][(nq & 1) * 2], b[nq >> 1][(nq & 1) * 2 + 1]);
        }

        if (kc == KCH - 1) {
            const int jb = rule0 + t * BN;
            #pragma unroll
            for (int mi = 0; mi < 2; ++mi) {
                #pragma unroll
                for (int h = 0; h < 2; ++h) {
                    const int r = wm + mi * 16 + (lane >> 2) + h * 8;
                    float cthr = vthr[r];   // monotone threshold: stale => only extra inserts
                    #pragma unroll
                    for (int nq = 0; nq < 4; ++nq) {
                        #pragma unroll
                        for (int e = 0; e < 2; ++e) {
                            float v = c[mi][nq][h * 2 + e];
                            int j = jb + wn + nq * 8 + (lane & 3) * 2 + e;
                            if (v > cthr && j < N_RULES) {
                                topk_insert(sm, r, v, j);
                                cthr = vthr[r];
                            }
                        }
                    }
                }
            }
        }

        if (++kc == KCH) { kc = 0; ++t; }
    }
    __syncthreads();

    // write per-row candidates (this half's top-8)
    for (int i = tid; i < BM * TOPK; i += NTHREADS) {
        int r = i >> 3, p = i & 7;
        g_topv[(size_t)(row0 + r) * NCAND + half * TOPK + p] = sm->topv[i];
        g_topi[(size_t)(row0 + r) * NCAND + half * TOPK + p] = sm->topi[i];
    }
}

// ---------------- epilogue: merge16 -> softmax -> gather -> gelu -> LN -----
#define ER 16
__global__ __launch_bounds__(256)
void epilogue_kernel(const float* __restrict__ s0,
                     const float* __restrict__ rules_raw,
                     const float* __restrict__ W,
                     const float* __restrict__ bvec,
                     const float* __restrict__ alpha_p,
                     const float* __restrict__ gamma,
                     const float* __restrict__ beta,
                     float* __restrict__ out) {
    __shared__ float ctx[ER][D_DIM];
    __shared__ float xs[ER][H_DIM];
    __shared__ float w8[ER][TOPK];
    __shared__ int   i8[ER][TOPK];
    __shared__ float mu_s[ER], rs_s[ER];

    const int tid = threadIdx.x;  // 256
    const int r0  = blockIdx.x * ER;

    if (tid < ER) {
        int r = r0 + tid;
        float cv[NCAND]; int ci[NCAND];
        #pragma unroll
        for (int q = 0; q < NCAND; ++q) {
            cv[q] = g_topv[(size_t)r * NCAND + q];
            ci[q] = g_topi[(size_t)r * NCAND + q];
        }
        float v[TOPK];
        #pragma unroll
        for (int p = 0; p < TOPK; ++p) {
            float bm = -FLT_MAX; int bq = 0;
            #pragma unroll
            for (int q = 0; q < NCAND; ++q)
                if (cv[q] > bm) { bm = cv[q]; bq = q; }
            v[p] = bm;
            #pragma unroll
            for (int q = 0; q < NCAND; ++q)
                if (q == bq) { i8[tid][p] = ci[q]; cv[q] = -FLT_MAX; }
        }
        float m = v[0];
        float s = 0.0f;
        #pragma unroll
        for (int p = 0; p < TOPK; ++p) { v[p] = expf(v[p] - m); s += v[p]; }
        float inv = 1.0f / s;
        #pragma unroll
        for (int p = 0; p < TOPK; ++p) w8[tid][p] = v[p] * inv;
    }
    __syncthreads();

    for (int e = tid; e < ER * D_DIM; e += 256) {
        int r = e / D_DIM, d = e - r * D_DIM;
        float acc = 0.0f;
        #pragma unroll
        for (int k = 0; k < TOPK; ++k) {
            int idx = i8[r][k];
            acc += w8[r][k] * rules_raw[(size_t)idx * D_DIM + d] * g_rinv[idx];
        }
        ctx[r][d] = acc;
    }
    __syncthreads();

    const float alpha = *alpha_p;
    const int h = tid;
    float acc[ER];
    #pragma unroll
    for (int r = 0; r < ER; ++r) acc[r] = 0.0f;

    const float4* wr = reinterpret_cast<const float4*>(W + (size_t)h * D_DIM);
    #pragma unroll 4
    for (int dq = 0; dq < D_DIM / 4; ++dq) {
        float4 w4 = wr[dq];
        #pragma unroll
        for (int r = 0; r < ER; ++r) {
            float4 c4 = *reinterpret_cast<const float4*>(&ctx[r][dq * 4]);
            acc[r] += w4.x * c4.x + w4.y * c4.y + w4.z * c4.z + w4.w * c4.w;
        }
    }
    const float bb = bvec[h];
    #pragma unroll
    for (int r = 0; r < ER; ++r) {
        float z = acc[r] + bb;
        float g = 0.5f * z * (1.0f + erff(z * 0.70710678118654752f));
        xs[r][h] = s0[(size_t)(r0 + r) * H_DIM + h] + alpha * g;
    }
    __syncthreads();

    const int w = tid >> 5, lane = tid & 31;
    for (int rr = w; rr < ER; rr += 8) {
        float s = 0.0f, s2 = 0.0f;
        #pragma unroll
        for (int q = 0; q < 8; ++q) {
            float x = xs[rr][lane + 32 * q];
            s += x; s2 += x * x;
        }
        for (int o = 16; o; o >>= 1) {
            s  += __shfl_xor_sync(0xffffffffu, s, o);
            s2 += __shfl_xor_sync(0xffffffffu, s2, o);
        }
        if (lane == 0) {
            float mu  = s * (1.0f / 256.0f);
            float var = s2 * (1.0f / 256.0f) - mu * mu;
            mu_s[rr] = mu;
            rs_s[rr] = rsqrtf(var + 1e-5f);
        }
    }
    __syncthreads();

    const float gm = gamma[h], bt = beta[h];
    #pragma unroll
    for (int r = 0; r < ER; ++r)
        out[(size_t)(r0 + r) * H_DIM + h] = (xs[r][h] - mu_s[r]) * rs_s[r] * gm + bt;
}

// ---------------- launch ----------------------------------------------------
extern "C" void kernel_launch(void* const* d_in, const int* in_sizes, int n_in,
                              void* d_out, int out_size) {
    const float* embeddings = (const float*)d_in[0];
    const float* s0         = (const float*)d_in[1];
    const float* rules      = (const float*)d_in[2];
    const float* W          = (const float*)d_in[3];
    const float* b          = (const float*)d_in[4];
    const float* alpha      = (const float*)d_in[5];
    const float* gamma      = (const float*)d_in[6];
    const float* beta       = (const float*)d_in[7];
    float* out = (float*)d_out;
    (void)in_sizes; (void)n_in; (void)out_size;

    cudaFuncSetAttribute(sims_topk_kernel,
                         cudaFuncAttributeMaxDynamicSharedMemorySize,
                         (int)sizeof(SimsSmem));

    prep_rules_kernel<<<N_PAD, 128>>>(rules);
    prep_q_kernel<<<B_ROWS, 128>>>(embeddings);
    sims_topk_kernel<<<128, NTHREADS, sizeof(SimsSmem)>>>();
    epilogue_kernel<<<B_ROWS / ER, 256>>>(s0, rules, W, b, alpha, gamma, beta, out);
}